// round 5
// baseline (speedup 1.0000x reference)
#include <cuda_runtime.h>
#include <math.h>
#include <stdint.h>

#define MU      0.02f
#define MU2     (MU * MU)
#define NBINS   10
#define NMAX    4194304
#define NBMAX   1024
#define CHUNK   2048          // rows per work chunk (2048 chunks for n=4.19M)
#define TPB     256

// Scratch — __device__ globals (allocation-free rule).
__device__ float2       g_loss_buf[NMAX];             // (g, loss) per row, 32 MB
__device__ float        d_blk_min[NBMAX];
__device__ float        d_blk_max[NBMAX];
__device__ double       d_blk_loss[NBMAX][NBINS];
__device__ unsigned int d_blk_cnt[NBMAX][NBINS];
__device__ unsigned int d_bar;                        // monotonic barrier ticket (never reset)
__device__ unsigned int d_ctrA;                       // chunk counters (reset at kernel end)
__device__ unsigned int d_ctrB;

// ---------------------------------------------------------------------------
// Software grid barrier: monotonic ticket counter, wrap-safe compare.
// Safe across graph replays (no reset needed). Requires all blocks resident.
__device__ __forceinline__ void grid_barrier() {
    __syncthreads();
    if (threadIdx.x == 0) {
        __threadfence();                                   // release phase writes
        unsigned int ticket = atomicAdd(&d_bar, 1u);
        unsigned int target = (ticket / gridDim.x + 1u) * gridDim.x;
        while ((int)(*(volatile unsigned int*)&d_bar - target) < 0) { }
        __threadfence();                                   // acquire remote writes
    }
    __syncthreads();
}

// Per-row math: rsqrt-based (MUFU.RSQ), ~2e-7 rel err, far under 1e-3 budget.
__device__ __forceinline__ float2 row_gl(float4 a, float4 b) {
    float d0 = a.x - b.x, d1 = a.y - b.y, d2 = a.z - b.z, d3 = a.w - b.w;
    float x0 = fmaf(d0, d0, MU2), x1 = fmaf(d1, d1, MU2);
    float x2 = fmaf(d2, d2, MU2), x3 = fmaf(d3, d3, MU2);
    float r0 = rsqrtf(x0), r1 = rsqrtf(x1), r2 = rsqrtf(x2), r3 = rsqrtf(x3);
    float loss = ((x0 * r0 - MU) + (x1 * r1 - MU)) + ((x2 * r2 - MU) + (x3 * r3 - MU));
    float g    = ((fabsf(d0) * r0 + fabsf(d1) * r1) + (fabsf(d2) * r2 + fabsf(d3) * r3));
    return make_float2(g, loss);
}

// ---------------------------------------------------------------------------
__global__ __launch_bounds__(TPB, 4)
void ghmr_fused(const float4* __restrict__ in, const float4* __restrict__ tg,
                float* __restrict__ out, int n) {
    const int lane = threadIdx.x & 31;
    const int wid  = threadIdx.x >> 5;
    const int nchunks = (n + CHUNK - 1) / CHUNK;

    __shared__ float s_w0[8], s_w1[8];
    __shared__ float s_range;
    __shared__ int   s_chunk;

    // ========== Phase A: g/loss + min/max, dynamic chunk scheduling ==========
    float lmin = __int_as_float(0x7F800000);   // +inf
    float lmax = 0.0f;

    for (;;) {
        if (threadIdx.x == 0) s_chunk = (int)atomicAdd(&d_ctrA, 1u);
        __syncthreads();
        int c = s_chunk;
        __syncthreads();                 // s_chunk consumed before next overwrite
        if (c >= nchunks) break;

        int base = c * CHUNK;
        int end  = min(base + CHUNK, n);
        int i    = base + threadIdx.x;
        for (; i + TPB < end; i += 2 * TPB) {
            float4 a0 = __ldcs(&in[i]);       float4 b0 = __ldcs(&tg[i]);
            float4 a1 = __ldcs(&in[i + TPB]); float4 b1 = __ldcs(&tg[i + TPB]);
            float2 v0 = row_gl(a0, b0);
            float2 v1 = row_gl(a1, b1);
            g_loss_buf[i]       = v0;
            g_loss_buf[i + TPB] = v1;
            lmin = fminf(lmin, fminf(v0.x, v1.x));
            lmax = fmaxf(lmax, fmaxf(v0.x, v1.x));
        }
        for (; i < end; i += TPB) {
            float2 v = row_gl(__ldcs(&in[i]), __ldcs(&tg[i]));
            g_loss_buf[i] = v;
            lmin = fminf(lmin, v.x);
            lmax = fmaxf(lmax, v.x);
        }
    }

    #pragma unroll
    for (int o = 16; o > 0; o >>= 1) {
        lmin = fminf(lmin, __shfl_xor_sync(0xFFFFFFFFu, lmin, o));
        lmax = fmaxf(lmax, __shfl_xor_sync(0xFFFFFFFFu, lmax, o));
    }
    if (lane == 0) { s_w0[wid] = lmin; s_w1[wid] = lmax; }
    __syncthreads();
    if (wid == 0) {
        lmin = (lane < 8) ? s_w0[lane] : __int_as_float(0x7F800000);
        lmax = (lane < 8) ? s_w1[lane] : 0.0f;
        #pragma unroll
        for (int o = 4; o > 0; o >>= 1) {
            lmin = fminf(lmin, __shfl_xor_sync(0xFFFFFFFFu, lmin, o));
            lmax = fmaxf(lmax, __shfl_xor_sync(0xFFFFFFFFu, lmax, o));
        }
        if (lane == 0) {
            d_blk_min[blockIdx.x] = lmin;   // plain overwrite, no reset needed
            d_blk_max[blockIdx.x] = lmax;
        }
    }

    grid_barrier();

    // ============ All blocks reduce global min/max from block slots ============
    {
        float m = __int_as_float(0x7F800000), M = 0.0f;
        for (int r = threadIdx.x; r < (int)gridDim.x; r += blockDim.x) {
            m = fminf(m, d_blk_min[r]);
            M = fmaxf(M, d_blk_max[r]);
        }
        #pragma unroll
        for (int o = 16; o > 0; o >>= 1) {
            m = fminf(m, __shfl_xor_sync(0xFFFFFFFFu, m, o));
            M = fmaxf(M, __shfl_xor_sync(0xFFFFFFFFu, M, o));
        }
        __syncthreads();
        if (lane == 0) { s_w0[wid] = m; s_w1[wid] = M; }
        __syncthreads();
        if (threadIdx.x == 0) {
            float gm = s_w0[0], gM = s_w1[0];
            #pragma unroll
            for (int w = 1; w < 8; w++) { gm = fminf(gm, s_w0[w]); gM = fmaxf(gM, s_w1[w]); }
            s_range = gM - gm;
        }
        __syncthreads();
    }
    const float range = s_range;

    // ===== Phase B: register histogram over scratch, dynamic chunks ==========
    float        acc[NBINS];
    unsigned int cnt[NBINS];
    #pragma unroll
    for (int b = 0; b < NBINS; b++) { acc[b] = 0.0f; cnt[b] = 0u; }

    for (;;) {
        if (threadIdx.x == 0) s_chunk = (int)atomicAdd(&d_ctrB, 1u);
        __syncthreads();
        int c = s_chunk;
        __syncthreads();
        if (c >= nchunks) break;

        int base = c * CHUNK;
        int end  = min(base + CHUNK, n);
        int j    = base + threadIdx.x;
        for (; j + TPB < end; j += 2 * TPB) {
            float2 v0 = g_loss_buf[j];
            float2 v1 = g_loss_buf[j + TPB];
            int b0 = min(max((int)floorf((v0.x / range) * (float)NBINS), 0), NBINS - 1);
            int b1 = min(max((int)floorf((v1.x / range) * (float)NBINS), 0), NBINS - 1);
            #pragma unroll
            for (int k = 0; k < NBINS; k++) {          // predicated select, no local mem
                if (k == b0) { acc[k] += v0.y; cnt[k]++; }
                if (k == b1) { acc[k] += v1.y; cnt[k]++; }
            }
        }
        for (; j < end; j += TPB) {
            float2 v = g_loss_buf[j];
            int b = min(max((int)floorf((v.x / range) * (float)NBINS), 0), NBINS - 1);
            #pragma unroll
            for (int k = 0; k < NBINS; k++) {
                if (k == b) { acc[k] += v.y; cnt[k]++; }
            }
        }
    }

    // warp-reduce each bin, then cross-warp via smem, write per-block slots
    __shared__ float        s_acc[8][NBINS];
    __shared__ unsigned int s_cnt[8][NBINS];
    #pragma unroll
    for (int b = 0; b < NBINS; b++) {
        float        a = acc[b];
        unsigned int c = cnt[b];
        #pragma unroll
        for (int o = 16; o > 0; o >>= 1) {
            a += __shfl_xor_sync(0xFFFFFFFFu, a, o);
            c += __shfl_xor_sync(0xFFFFFFFFu, c, o);
        }
        if (lane == 0) { s_acc[wid][b] = a; s_cnt[wid][b] = c; }
    }
    __syncthreads();
    if (threadIdx.x < NBINS) {
        double       s = 0.0;
        unsigned int c = 0u;
        #pragma unroll
        for (int w = 0; w < 8; w++) { s += (double)s_acc[w][threadIdx.x]; c += s_cnt[w][threadIdx.x]; }
        d_blk_loss[blockIdx.x][threadIdx.x] = s;
        d_blk_cnt[blockIdx.x][threadIdx.x]  = c;
    }

    grid_barrier();

    // ======================= Phase C: block 0 finalizes =======================
    if (blockIdx.x == 0) {
        if (wid == 0) {
            double       s = 0.0;
            unsigned int c = 0u;
            if (lane < NBINS) {
                double s0 = 0, s1 = 0, s2 = 0, s3 = 0;
                unsigned int c0 = 0, c1 = 0, c2 = 0, c3 = 0;
                int nb = (int)gridDim.x;
                int r = 0;
                for (; r + 3 < nb; r += 4) {
                    s0 += d_blk_loss[r][lane];     c0 += d_blk_cnt[r][lane];
                    s1 += d_blk_loss[r + 1][lane]; c1 += d_blk_cnt[r + 1][lane];
                    s2 += d_blk_loss[r + 2][lane]; c2 += d_blk_cnt[r + 2][lane];
                    s3 += d_blk_loss[r + 3][lane]; c3 += d_blk_cnt[r + 3][lane];
                }
                for (; r < nb; r++) { s0 += d_blk_loss[r][lane]; c0 += d_blk_cnt[r][lane]; }
                s = (s0 + s1) + (s2 + s3);
                c = (c0 + c1) + (c2 + c3);
            }
            double contrib = (c > 0u) ? s / (double)c : 0.0;   // 1 fp64 div/lane, parallel
            int    ne      = (c > 0u) ? 1 : 0;
            #pragma unroll
            for (int o = 16; o > 0; o >>= 1) {
                contrib += __shfl_xor_sync(0xFFFFFFFFu, contrib, o);
                ne      += __shfl_xor_sync(0xFFFFFFFFu, ne, o);
            }
            if (lane == 0) {
                if (ne < 1) ne = 1;
                out[0] = (float)(contrib / (double)ne / 64.0 / 4096.0);
                // Reset chunk counters for the next graph replay. All blocks have
                // passed the final barrier, so no one touches these anymore.
                d_ctrA = 0u;
                d_ctrB = 0u;
                __threadfence();
            }
        }
    }
}

// ---------------------------------------------------------------------------
extern "C" void kernel_launch(void* const* d_in, const int* in_sizes, int n_in,
                              void* d_out, int out_size) {
    const float4* in = (const float4*)d_in[0];
    const float4* tg = (const float4*)d_in[1];
    int n = in_sizes[0] / 4;           // rows (channels = 4)
    if (n > NMAX) n = NMAX;

    int sm = 0;
    if (cudaDeviceGetAttribute(&sm, cudaDevAttrMultiProcessorCount, 0) != cudaSuccess || sm <= 0)
        sm = 148;
    int nb = 4 * sm;                   // __launch_bounds__(256,4) guarantees co-residency
    if (nb > NBMAX) nb = NBMAX;

    ghmr_fused<<<nb, TPB>>>(in, tg, (float*)d_out, n);
}

// round 7
// speedup vs baseline: 1.2143x; 1.2143x over previous
#include <cuda_runtime.h>
#include <math.h>
#include <stdint.h>

#define MU    0.02f
#define MU2   (MU * MU)
#define NBINS 10
#define NMAX  4194304
#define NB1   4096            // k1 grid (slots)
#define NB2   2048            // k2 grid (slots)
#define TPB   256

// Scratch — __device__ globals (allocation-free rule). float4 packs two rows:
// {g0, loss0, g1, loss1}. 16B-aligned by type.
__device__ float4       g_buf[NMAX / 2];              // 32 MB
__device__ float        d_blk_min[NB1];
__device__ float        d_blk_max[NB1];
__device__ double       d_blk_loss[NB2][NBINS];
__device__ unsigned int d_blk_cnt[NB2][NBINS];

// ---------------------------------------------------------------------------
// Math per row: rsqrt-based (MUFU.RSQ), ~2e-7 rel err (measured rel_err 0.0).
__device__ __forceinline__ void row_gl(float4 a, float4 b, float& g, float& loss) {
    float d0 = a.x - b.x, d1 = a.y - b.y, d2 = a.z - b.z, d3 = a.w - b.w;
    float x0 = fmaf(d0, d0, MU2), x1 = fmaf(d1, d1, MU2);
    float x2 = fmaf(d2, d2, MU2), x3 = fmaf(d3, d3, MU2);
    float r0 = rsqrtf(x0), r1 = rsqrtf(x1), r2 = rsqrtf(x2), r3 = rsqrtf(x3);
    loss = ((x0 * r0 - MU) + (x1 * r1 - MU)) + ((x2 * r2 - MU) + (x3 * r3 - MU));
    g    = ((fabsf(d0) * r0 + fabsf(d1) * r1) + (fabsf(d2) * r2 + fabsf(d3) * r3));
}

// ---------------------------------------------------------------------------
// k1: compute (g, loss) for all rows, write packed scratch, per-block min/max.
// Thread handles row pair p -> 4x LDG.128 + 1x STG.128 per iteration.
__global__ __launch_bounds__(TPB)
void ghmr_k1(const float4* __restrict__ in, const float4* __restrict__ tg,
             int n) {
    const int tid    = blockIdx.x * blockDim.x + threadIdx.x;
    const int stride = gridDim.x * blockDim.x;
    const int lane   = threadIdx.x & 31;
    const int wid    = threadIdx.x >> 5;
    const int npairs = n >> 1;

    float lmin = __int_as_float(0x7F800000);   // +inf
    float lmax = 0.0f;

    for (int p = tid; p < npairs; p += stride) {
        int r = p << 1;
        float4 a0 = __ldcs(&in[r]);     float4 b0 = __ldcs(&tg[r]);
        float4 a1 = __ldcs(&in[r + 1]); float4 b1 = __ldcs(&tg[r + 1]);
        float g0, l0, g1, l1;
        row_gl(a0, b0, g0, l0);
        row_gl(a1, b1, g1, l1);
        g_buf[p] = make_float4(g0, l0, g1, l1);
        lmin = fminf(lmin, fminf(g0, g1));
        lmax = fmaxf(lmax, fmaxf(g0, g1));
    }
    // odd tail row (n odd): handled by global thread 0, stored in pair slot npairs
    if ((n & 1) && tid == 0) {
        int r = n - 1;
        float g0, l0;
        row_gl(__ldcs(&in[r]), __ldcs(&tg[r]), g0, l0);
        g_buf[npairs] = make_float4(g0, l0, g0, 0.0f);  // duplicate g ok for min/max; loss1=0 unused
        lmin = fminf(lmin, g0);
        lmax = fmaxf(lmax, g0);
    }

    __shared__ float s_w0[8], s_w1[8];
    #pragma unroll
    for (int o = 16; o > 0; o >>= 1) {
        lmin = fminf(lmin, __shfl_xor_sync(0xFFFFFFFFu, lmin, o));
        lmax = fmaxf(lmax, __shfl_xor_sync(0xFFFFFFFFu, lmax, o));
    }
    if (lane == 0) { s_w0[wid] = lmin; s_w1[wid] = lmax; }
    __syncthreads();
    if (wid == 0) {
        lmin = (lane < 8) ? s_w0[lane] : __int_as_float(0x7F800000);
        lmax = (lane < 8) ? s_w1[lane] : 0.0f;
        #pragma unroll
        for (int o = 4; o > 0; o >>= 1) {
            lmin = fminf(lmin, __shfl_xor_sync(0xFFFFFFFFu, lmin, o));
            lmax = fmaxf(lmax, __shfl_xor_sync(0xFFFFFFFFu, lmax, o));
        }
        if (lane == 0) {
            d_blk_min[blockIdx.x] = lmin;   // plain overwrite each launch — no init needed
            d_blk_max[blockIdx.x] = lmax;
        }
    }
}

// ---------------------------------------------------------------------------
// k2: redundant slot-reduce for global range (L2-fed, ~16 loads/thread), then
// register-accumulator histogram over the packed scratch.
__global__ __launch_bounds__(TPB)
void ghmr_k2(int n) {
    const int tid    = blockIdx.x * blockDim.x + threadIdx.x;
    const int stride = gridDim.x * blockDim.x;
    const int lane   = threadIdx.x & 31;
    const int wid    = threadIdx.x >> 5;

    __shared__ float s_w0[8], s_w1[8];
    __shared__ float s_range;

    // ---- global min/max from k1's 4096 slots ----
    {
        float m = __int_as_float(0x7F800000), M = 0.0f;
        for (int r = threadIdx.x; r < NB1; r += TPB) {
            m = fminf(m, d_blk_min[r]);
            M = fmaxf(M, d_blk_max[r]);
        }
        #pragma unroll
        for (int o = 16; o > 0; o >>= 1) {
            m = fminf(m, __shfl_xor_sync(0xFFFFFFFFu, m, o));
            M = fmaxf(M, __shfl_xor_sync(0xFFFFFFFFu, M, o));
        }
        if (lane == 0) { s_w0[wid] = m; s_w1[wid] = M; }
        __syncthreads();
        if (threadIdx.x == 0) {
            float gm = s_w0[0], gM = s_w1[0];
            #pragma unroll
            for (int w = 1; w < 8; w++) { gm = fminf(gm, s_w0[w]); gM = fmaxf(gM, s_w1[w]); }
            s_range = gM - gm;
        }
        __syncthreads();
    }
    const float range = s_range;

    // ---- histogram ----
    float        acc[NBINS];
    unsigned int cnt[NBINS];
    #pragma unroll
    for (int b = 0; b < NBINS; b++) { acc[b] = 0.0f; cnt[b] = 0u; }

    const int npairs = n >> 1;
    for (int p = tid; p < npairs; p += stride) {
        float4 v = g_buf[p];
        int b0 = min(max((int)floorf((v.x / range) * (float)NBINS), 0), NBINS - 1);
        int b1 = min(max((int)floorf((v.z / range) * (float)NBINS), 0), NBINS - 1);
        #pragma unroll
        for (int k = 0; k < NBINS; k++) {              // predicated select, no local mem
            if (k == b0) { acc[k] += v.y; cnt[k]++; }
            if (k == b1) { acc[k] += v.w; cnt[k]++; }
        }
    }
    if ((n & 1) && tid == 0) {
        float4 v = g_buf[npairs];
        int b0 = min(max((int)floorf((v.x / range) * (float)NBINS), 0), NBINS - 1);
        #pragma unroll
        for (int k = 0; k < NBINS; k++) {
            if (k == b0) { acc[k] += v.y; cnt[k]++; }
        }
    }

    // warp-reduce, cross-warp via smem, write per-block slots
    __shared__ float        s_acc[8][NBINS];
    __shared__ unsigned int s_cnt[8][NBINS];
    #pragma unroll
    for (int b = 0; b < NBINS; b++) {
        float        a = acc[b];
        unsigned int c = cnt[b];
        #pragma unroll
        for (int o = 16; o > 0; o >>= 1) {
            a += __shfl_xor_sync(0xFFFFFFFFu, a, o);
            c += __shfl_xor_sync(0xFFFFFFFFu, c, o);
        }
        if (lane == 0) { s_acc[wid][b] = a; s_cnt[wid][b] = c; }
    }
    __syncthreads();
    if (threadIdx.x < NBINS) {
        double       s = 0.0;
        unsigned int c = 0u;
        #pragma unroll
        for (int w = 0; w < 8; w++) { s += (double)s_acc[w][threadIdx.x]; c += s_cnt[w][threadIdx.x]; }
        d_blk_loss[blockIdx.x][threadIdx.x] = s;
        d_blk_cnt[blockIdx.x][threadIdx.x]  = c;
    }
}

// ---------------------------------------------------------------------------
// k3: finalize. One warp per bin (warps 0..9), 1 fp64 divide per warp in
// parallel; thread 0 combines.
__global__ __launch_bounds__(320)
void ghmr_k3(float* __restrict__ out) {
    const int lane = threadIdx.x & 31;
    const int wid  = threadIdx.x >> 5;

    __shared__ double s_con[NBINS];
    __shared__ int    s_ne[NBINS];

    if (wid < NBINS) {
        const int b = wid;
        double s0 = 0, s1 = 0;
        unsigned int c0 = 0, c1 = 0;
        for (int r = lane; r < NB2; r += 64) {         // 2-way ILP on the DADD chain
            s0 += d_blk_loss[r][b];        c0 += d_blk_cnt[r][b];
            s1 += d_blk_loss[r + 32][b];   c1 += d_blk_cnt[r + 32][b];
        }
        double s = s0 + s1;
        unsigned int c = c0 + c1;
        #pragma unroll
        for (int o = 16; o > 0; o >>= 1) {
            s += __shfl_xor_sync(0xFFFFFFFFu, s, o);
            c += __shfl_xor_sync(0xFFFFFFFFu, c, o);
        }
        if (lane == 0) {
            s_con[b] = (c > 0u) ? s / (double)c : 0.0;
            s_ne[b]  = (c > 0u) ? 1 : 0;
        }
    }
    __syncthreads();
    if (threadIdx.x == 0) {
        double s = 0.0;
        int    ne = 0;
        #pragma unroll
        for (int b = 0; b < NBINS; b++) { s += s_con[b]; ne += s_ne[b]; }
        if (ne < 1) ne = 1;
        out[0] = (float)(s / (double)ne / 64.0 / 4096.0);
    }
}

// ---------------------------------------------------------------------------
extern "C" void kernel_launch(void* const* d_in, const int* in_sizes, int n_in,
                              void* d_out, int out_size) {
    const float4* in = (const float4*)d_in[0];
    const float4* tg = (const float4*)d_in[1];
    int n = in_sizes[0] / 4;           // rows (channels = 4)
    if (n > NMAX) n = NMAX;

    ghmr_k1<<<NB1, TPB>>>(in, tg, n);
    ghmr_k2<<<NB2, TPB>>>(n);
    ghmr_k3<<<1, 320>>>((float*)d_out);
}